// round 1
// baseline (speedup 1.0000x reference)
#include <cuda_runtime.h>
#include <math.h>
#include <stdint.h>

#define G 4096
#define D 128
#define NOUT 512

#define NEG_BIG (-3.402823466e+38f)

// ---------- static device scratch ----------
__device__ float g_WcT[256 * 512];   // combined weight, k-major: WcT[k][n]
__device__ float g_bias[512];
__device__ float g_h[G * D];
__device__ float g_c[G * D];
__device__ float g_r[G * D];
__device__ float g_gates[G * NOUT];
__device__ float g_h1[D];
__device__ float g_c1[D];
__device__ float g_g1base[512];
__device__ int   g_segofs[G + 1];

__device__ __forceinline__ float sigf(float x) { return 1.f / (1.f + __expf(-x)); }

// ---------- setup kernels ----------
// Wc[n][k] = W_ih[n][k] + (k<128 ? W_hh[n][k] : 0); store transposed (k-major).
__global__ void prep_weights(const float* __restrict__ W_ih, const float* __restrict__ W_hh,
                             const float* __restrict__ b_ih, const float* __restrict__ b_hh) {
    int idx = blockIdx.x * blockDim.x + threadIdx.x;
    if (idx < 256 * 512) {
        int k = idx >> 9, n = idx & 511;
        float w = W_ih[n * 256 + k];
        if (k < 128) w += W_hh[n * 128 + k];
        g_WcT[k * 512 + n] = w;
    }
    if (idx < 512) g_bias[idx] = b_ih[idx] + b_hh[idx];
}

// Segment boundaries via binary search (index is sorted). Detect int32 vs int64 at runtime.
__global__ void seg_bounds(const int* __restrict__ idx32, int N) {
    int g = blockIdx.x * blockDim.x + threadIdx.x;
    if (g > G) return;
    int j = ((N - 1) & 1) ? (N - 1) : (N - 2);
    bool is64 = (idx32[j] == 0);   // high word of an int64 element (values < 4096) is 0
    const long long* idx64 = (const long long*)idx32;
    int lo = 0, hi = N;
    while (lo < hi) {
        int mid = (lo + hi) >> 1;
        long long v = is64 ? idx64[mid] : (long long)idx32[mid];
        if (v < (long long)g) lo = mid + 1; else hi = mid;
    }
    g_segofs[g] = lo;
}

// Step 1 closed form: state is 0, so gates = bias (same for every row).
__global__ void step1_vec() {
    int d = threadIdx.x;
    if (d < D) {
        float i = g_bias[d], f = g_bias[128 + d], gg = g_bias[256 + d], o = g_bias[384 + d];
        (void)f;
        float c = sigf(i) * tanhf(gg);      // sig(f)*0 + sig(i)*tanh(g)
        g_c1[d] = c;
        g_h1[d] = sigf(o) * tanhf(c);
    }
}

// g1base[n] = bias[n] + sum_{k<128} h1[k] * WcT[k][n]  (rank-1 broadcast part of step 2)
__global__ void g1base_kernel() {
    int n = blockIdx.x * blockDim.x + threadIdx.x;
    if (n >= 512) return;
    float acc = g_bias[n];
    #pragma unroll 8
    for (int k = 0; k < 128; k++) acc += g_h1[k] * g_WcT[k * 512 + n];
    g_g1base[n] = acc;
}

// ---------- GEMM: gates[m][n] = base[n] + (HAS_A1 ? h@WcT[0:128] : 0) + r@WcT[128:256] ----------
// 64x64 tile, 256 threads, 4x4 microtile, BK=16.
template <bool HAS_A1>
__global__ void __launch_bounds__(256) gemm_gates() {
    __shared__ float As[16][64];
    __shared__ float Bs[16][64];
    int bm = blockIdx.x;             // 0..63
    int bn = blockIdx.y;             // 0..7
    int t = threadIdx.x;
    int tm = t >> 4, tn = t & 15;
    float acc[4][4] = {};

    const int kb0 = HAS_A1 ? 0 : 128;
    for (int kb = kb0; kb < 256; kb += 16) {
        const float* A = (kb < 128) ? g_h : g_r;
        int klocal = (kb < 128) ? kb : (kb - 128);
        {
            int row = t >> 2, kg = (t & 3) << 2;
            float4 v = *(const float4*)&A[(bm * 64 + row) * 128 + klocal + kg];
            As[kg + 0][row] = v.x; As[kg + 1][row] = v.y;
            As[kg + 2][row] = v.z; As[kg + 3][row] = v.w;
        }
        {
            int kk = t >> 4, nc = (t & 15) << 2;
            *(float4*)&Bs[kk][nc] = *(const float4*)&g_WcT[(kb + kk) * 512 + bn * 64 + nc];
        }
        __syncthreads();
        #pragma unroll
        for (int kk = 0; kk < 16; kk++) {
            float4 a4 = *(const float4*)&As[kk][tm << 2];
            float4 b4 = *(const float4*)&Bs[kk][tn << 2];
            acc[0][0] += a4.x * b4.x; acc[0][1] += a4.x * b4.y; acc[0][2] += a4.x * b4.z; acc[0][3] += a4.x * b4.w;
            acc[1][0] += a4.y * b4.x; acc[1][1] += a4.y * b4.y; acc[1][2] += a4.y * b4.z; acc[1][3] += a4.y * b4.w;
            acc[2][0] += a4.z * b4.x; acc[2][1] += a4.z * b4.y; acc[2][2] += a4.z * b4.z; acc[2][3] += a4.z * b4.w;
            acc[3][0] += a4.w * b4.x; acc[3][1] += a4.w * b4.y; acc[3][2] += a4.w * b4.z; acc[3][3] += a4.w * b4.w;
        }
        __syncthreads();
    }

    const float* base = HAS_A1 ? g_bias : g_g1base;
    int n0 = bn * 64 + (tn << 2);
    float4 b4 = *(const float4*)&base[n0];
    #pragma unroll
    for (int i = 0; i < 4; i++) {
        int m = bm * 64 + (tm << 2) + i;
        float4 o;
        o.x = acc[i][0] + b4.x; o.y = acc[i][1] + b4.y;
        o.z = acc[i][2] + b4.z; o.w = acc[i][3] + b4.w;
        *(float4*)&g_gates[m * 512 + n0] = o;
    }
}

// ---------- LSTM elementwise: c,h from gates ----------
template <bool CVEC>
__global__ void lstm_elem() {
    int idx = blockIdx.x * blockDim.x + threadIdx.x;
    if (idx >= G * D) return;
    int m = idx >> 7, d = idx & 127;
    const float* gm = &g_gates[m * 512];
    float i = gm[d], f = gm[128 + d], gg = gm[256 + d], o = gm[384 + d];
    float cold = CVEC ? g_c1[d] : g_c[idx];
    float c = sigf(f) * cold + sigf(i) * tanhf(gg);
    g_c[idx] = c;
    g_h[idx] = sigf(o) * tanhf(c);
}

// ---------- attention: per-segment online softmax, single pass over x ----------
// One block per segment g. 8 warps; warp w handles rows start+w, start+w+8, ...
// Lane l owns columns 4l..4l+3.
template <bool QBCAST, bool FINAL>
__global__ void __launch_bounds__(256) attn_kernel(const float* __restrict__ x,
                                                   float* __restrict__ out) {
    int g = blockIdx.x;
    int start = g_segofs[g], end = g_segofs[g + 1];
    int t = threadIdx.x, w = t >> 5, l = t & 31;
    const float* qrow = QBCAST ? g_h1 : (g_h + g * D);
    float4 qv = *(const float4*)&qrow[l << 2];

    float m = NEG_BIG, s = 0.f;
    float4 acc = make_float4(0.f, 0.f, 0.f, 0.f);

    for (int n = start + w; n < end; n += 8) {
        float4 xv = *(const float4*)&x[(size_t)n * D + (l << 2)];
        float e = xv.x * qv.x + xv.y * qv.y + xv.z * qv.z + xv.w * qv.w;
        e += __shfl_xor_sync(0xffffffffu, e, 16);
        e += __shfl_xor_sync(0xffffffffu, e, 8);
        e += __shfl_xor_sync(0xffffffffu, e, 4);
        e += __shfl_xor_sync(0xffffffffu, e, 2);
        e += __shfl_xor_sync(0xffffffffu, e, 1);
        float mn = fmaxf(m, e);
        float sc = __expf(m - mn);        // m==NEG_BIG -> underflows to 0
        float p  = __expf(e - mn);
        s = s * sc + p;
        acc.x = acc.x * sc + p * xv.x;
        acc.y = acc.y * sc + p * xv.y;
        acc.z = acc.z * sc + p * xv.z;
        acc.w = acc.w * sc + p * xv.w;
        m = mn;
    }

    __shared__ float sm_m[8], sm_s[8];
    __shared__ float sm_acc[8][128];
    if (l == 0) { sm_m[w] = m; sm_s[w] = s; }
    *(float4*)&sm_acc[w][l << 2] = acc;
    __syncthreads();

    if (t < 128) {
        float M = NEG_BIG;
        #pragma unroll
        for (int ww = 0; ww < 8; ww++) M = fmaxf(M, sm_m[ww]);
        float r = 0.f;
        if (M != NEG_BIG) {
            float stot = 0.f, racc = 0.f;
            #pragma unroll
            for (int ww = 0; ww < 8; ww++) {
                float fsc = __expf(sm_m[ww] - M);
                stot += fsc * sm_s[ww];
                racc += fsc * sm_acc[ww][t];
            }
            r = racc / fmaxf(stot, 1e-16f);
        }
        if (FINAL) {
            out[(size_t)g * 256 + 128 + t] = r;
            out[(size_t)g * 256 + t] = qrow[t];
        } else {
            g_r[g * D + t] = r;
        }
    }
}

// ---------- launch ----------
extern "C" void kernel_launch(void* const* d_in, const int* in_sizes, int n_in,
                              void* d_out, int out_size) {
    const float* x    = (const float*)d_in[0];
    const float* W_ih = (const float*)d_in[1];
    const float* W_hh = (const float*)d_in[2];
    const float* b_ih = (const float*)d_in[3];
    const float* b_hh = (const float*)d_in[4];
    const int*   idx  = (const int*)d_in[5];    // int32 or int64, detected on device
    float* out = (float*)d_out;
    int N = in_sizes[5];
    (void)n_in; (void)out_size;

    // setup
    prep_weights<<<(256 * 512 + 255) / 256, 256>>>(W_ih, W_hh, b_ih, b_hh);
    seg_bounds<<<(G + 1 + 255) / 256, 256>>>(idx, N);
    step1_vec<<<1, 128>>>();

    // step 1: q = h1 (broadcast) -> r1
    attn_kernel<true, false><<<G, 256>>>(x, out);

    // step 2: gates = g1base + r1 @ WcT[128:256]
    g1base_kernel<<<1, 512>>>();
    gemm_gates<false><<<dim3(64, 8), 256>>>();
    lstm_elem<true><<<(G * D + 255) / 256, 256>>>();
    attn_kernel<false, false><<<G, 256>>>(x, out);

    // step 3: gates = bias + h2 @ WcT[0:128] + r2 @ WcT[128:256]
    gemm_gates<true><<<dim3(64, 8), 256>>>();
    lstm_elem<false><<<(G * D + 255) / 256, 256>>>();
    attn_kernel<false, true><<<G, 256>>>(x, out);
}

// round 2
// speedup vs baseline: 1.4300x; 1.4300x over previous
#include <cuda_runtime.h>
#include <math.h>
#include <stdint.h>

#define G 4096
#define D 128

#define NEG_BIG (-3.402823466e+38f)
#define LOG2E 1.44269504088896340736f

// ---------- static device scratch ----------
__device__ float g_WcT[256 * 512];   // combined weight, k-major, n' permuted: n' = d*4+gate
__device__ float g_bias[512];        // permuted bias
__device__ float g_h[G * D];
__device__ float g_c[G * D];
__device__ float g_r[G * D];
__device__ float g_h1[D];
__device__ float g_c1[D];
__device__ float g_g1base[512];      // permuted
__device__ int   g_segofs[G + 1];

__device__ __forceinline__ float sigf(float x) { return 1.f / (1.f + __expf(-x)); }

__device__ __forceinline__ float ex2(float x) {
    float r;
    asm("ex2.approx.ftz.f32 %0, %1;" : "=f"(r) : "f"(x));
    return r;
}

__device__ __forceinline__ unsigned long long fma2(unsigned long long a, unsigned long long b,
                                                   unsigned long long c) {
    unsigned long long d;
    asm("fma.rn.f32x2 %0, %1, %2, %3;" : "=l"(d) : "l"(a), "l"(b), "l"(c));
    return d;
}
__device__ __forceinline__ unsigned long long pack2(float v) {
    unsigned long long d;
    asm("mov.b64 %0, {%1, %1};" : "=l"(d) : "f"(v));
    return d;
}

// ---------- setup kernels ----------
__global__ void prep_weights(const float* __restrict__ W_ih, const float* __restrict__ W_hh,
                             const float* __restrict__ b_ih, const float* __restrict__ b_hh) {
    int idx = blockIdx.x * blockDim.x + threadIdx.x;
    if (idx < 256 * 512) {
        int k = idx >> 9, n = idx & 511;
        int gate = n >> 7, d = n & 127;
        float w = W_ih[n * 256 + k];
        if (k < 128) w += W_hh[n * 128 + k];
        g_WcT[k * 512 + d * 4 + gate] = w;
    }
    if (idx < 512) {
        int gate = idx >> 7, d = idx & 127;
        g_bias[d * 4 + gate] = b_ih[idx] + b_hh[idx];
    }
}

// Segment boundaries via binary search (index is sorted). Detect int32 vs int64 at runtime.
__global__ void seg_bounds(const int* __restrict__ idx32, int N) {
    int g = blockIdx.x * blockDim.x + threadIdx.x;
    if (g > G) return;
    int j = ((N - 1) & 1) ? (N - 1) : (N - 2);
    bool is64 = (idx32[j] == 0);
    const long long* idx64 = (const long long*)idx32;
    int lo = 0, hi = N;
    while (lo < hi) {
        int mid = (lo + hi) >> 1;
        long long v = is64 ? idx64[mid] : (long long)idx32[mid];
        if (v < (long long)g) lo = mid + 1; else hi = mid;
    }
    g_segofs[g] = lo;
}

// Step 1 closed form: state 0 -> gates = bias (same for every row).
__global__ void step1_vec() {
    int d = threadIdx.x;
    if (d < D) {
        float i = g_bias[d * 4 + 0], gg = g_bias[d * 4 + 2], o = g_bias[d * 4 + 3];
        float c = sigf(i) * tanhf(gg);
        g_c1[d] = c;
        g_h1[d] = sigf(o) * tanhf(c);
    }
}

// g1base[n'] = bias[n'] + sum_{k<128} h1[k] * WcT[k][n']
__global__ void g1base_kernel() {
    int n = blockIdx.x * blockDim.x + threadIdx.x;
    if (n >= 512) return;
    float acc = g_bias[n];
    #pragma unroll 8
    for (int k = 0; k < 128; k++) acc += g_h1[k] * g_WcT[k * 512 + n];
    g_g1base[n] = acc;
}

// ---------- fused GEMM + LSTM cell ----------
// gates[m][n'] = base[n'] + (HAS_A1 ? h@WcT[0:128] : 0) + r@WcT[128:256]
// then c,h computed in epilogue (gates for a given d are all in-block thanks to permutation).
// 128x128 tile, 256 threads, 8x8 microtile, BK=8, packed f32x2 FFMA.
template <bool HAS_A1, bool CVEC>
__global__ void __launch_bounds__(256) gemm_lstm() {
    __shared__ float As[8][128];
    __shared__ float Bs[8][128];
    int bm = blockIdx.x;             // 0..31
    int bn = blockIdx.y;             // 0..3
    int t = threadIdx.x;
    int tm = t >> 4, tn = t & 15;
    unsigned long long acc[8][4] = {};   // 8 rows x 4 col-pairs

    int arow = t >> 1, ak4 = (t & 1) * 4;
    int bkk = t >> 5, bnc = (t & 31) * 4;

    const int kb0 = HAS_A1 ? 0 : 128;
    for (int kb = kb0; kb < 256; kb += 8) {
        const float* A = (kb < 128) ? g_h : g_r;
        int kl = (kb & 127) + ak4;
        float4 av = *(const float4*)&A[(size_t)(bm * 128 + arow) * 128 + kl];
        As[ak4 + 0][arow] = av.x; As[ak4 + 1][arow] = av.y;
        As[ak4 + 2][arow] = av.z; As[ak4 + 3][arow] = av.w;
        *(float4*)&Bs[bkk][bnc] = *(const float4*)&g_WcT[(kb + bkk) * 512 + bn * 128 + bnc];
        __syncthreads();
        #pragma unroll
        for (int kk = 0; kk < 8; kk++) {
            float4 a0 = *(const float4*)&As[kk][tm * 4];
            float4 a1 = *(const float4*)&As[kk][64 + tm * 4];
            unsigned long long b0 = *(const unsigned long long*)&Bs[kk][tn * 4];
            unsigned long long b1 = *(const unsigned long long*)&Bs[kk][tn * 4 + 2];
            unsigned long long b2 = *(const unsigned long long*)&Bs[kk][64 + tn * 4];
            unsigned long long b3 = *(const unsigned long long*)&Bs[kk][64 + tn * 4 + 2];
            float am[8] = {a0.x, a0.y, a0.z, a0.w, a1.x, a1.y, a1.z, a1.w};
            #pragma unroll
            for (int mi = 0; mi < 8; mi++) {
                unsigned long long pa = pack2(am[mi]);
                acc[mi][0] = fma2(pa, b0, acc[mi][0]);
                acc[mi][1] = fma2(pa, b1, acc[mi][1]);
                acc[mi][2] = fma2(pa, b2, acc[mi][2]);
                acc[mi][3] = fma2(pa, b3, acc[mi][3]);
            }
        }
        __syncthreads();
    }

    // epilogue: thread covers d0 = bn*32+tn and d1 = d0+16, 8 m-rows.
    const float* base = HAS_A1 ? g_bias : g_g1base;
    int d0 = bn * 32 + tn, d1 = d0 + 16;
    float4 bz0 = *(const float4*)&base[bn * 128 + tn * 4];
    float4 bz1 = *(const float4*)&base[bn * 128 + 64 + tn * 4];
    float c1a = 0.f, c1b = 0.f;
    if (CVEC) { c1a = g_c1[d0]; c1b = g_c1[d1]; }
    #pragma unroll
    for (int mi = 0; mi < 8; mi++) {
        int m = bm * 128 + ((mi < 4) ? (tm * 4 + mi) : (64 + tm * 4 + mi - 4));
        {
            float2 p0 = *reinterpret_cast<float2*>(&acc[mi][0]);
            float2 p1 = *reinterpret_cast<float2*>(&acc[mi][1]);
            float gi = p0.x + bz0.x, gf = p0.y + bz0.y, gg = p1.x + bz0.z, go = p1.y + bz0.w;
            float cold = CVEC ? c1a : g_c[(size_t)m * 128 + d0];
            float c = sigf(gf) * cold + sigf(gi) * tanhf(gg);
            g_c[(size_t)m * 128 + d0] = c;
            g_h[(size_t)m * 128 + d0] = sigf(go) * tanhf(c);
        }
        {
            float2 p0 = *reinterpret_cast<float2*>(&acc[mi][2]);
            float2 p1 = *reinterpret_cast<float2*>(&acc[mi][3]);
            float gi = p0.x + bz1.x, gf = p0.y + bz1.y, gg = p1.x + bz1.z, go = p1.y + bz1.w;
            float cold = CVEC ? c1b : g_c[(size_t)m * 128 + d1];
            float c = sigf(gf) * cold + sigf(gi) * tanhf(gg);
            g_c[(size_t)m * 128 + d1] = c;
            g_h[(size_t)m * 128 + d1] = sigf(go) * tanhf(c);
        }
    }
}

// ---------- attention: per-segment online softmax, single pass over x ----------
// One block (128 threads = 4 warps) per segment. Each warp handles 4 rows per iteration:
// lane l -> row group (l>>3), column set (l&7)*4 + 32j (j=0..3). Softmax state per lane.
template <bool QBCAST, bool FINAL>
__global__ void __launch_bounds__(128) attn_kernel(const float* __restrict__ x,
                                                   float* __restrict__ out) {
    int g = blockIdx.x;
    int start = g_segofs[g], end = g_segofs[g + 1];
    int t = threadIdx.x, w = t >> 5, l = t & 31;
    int i8 = l & 7, grp = l >> 3;
    const float* qrow = QBCAST ? g_h1 : (g_h + (size_t)g * D);

    float4 qv[4];
    #pragma unroll
    for (int j = 0; j < 4; j++) {
        float4 q = *(const float4*)&qrow[i8 * 4 + 32 * j];
        qv[j].x = q.x * LOG2E; qv[j].y = q.y * LOG2E;
        qv[j].z = q.z * LOG2E; qv[j].w = q.w * LOG2E;
    }

    float m = NEG_BIG, s = 0.f;
    float4 acc[4] = {};

    for (int r0 = start + w * 4; r0 < end; r0 += 16) {
        int row = r0 + grp;
        bool valid = row < end;
        int rowc = valid ? row : end - 1;
        const float* xr = x + (size_t)rowc * D + i8 * 4;
        float4 xv[4];
        #pragma unroll
        for (int j = 0; j < 4; j++) xv[j] = *(const float4*)&xr[32 * j];

        float e0 = xv[0].x * qv[0].x + xv[0].y * qv[0].y + xv[0].z * qv[0].z + xv[0].w * qv[0].w;
        float e1 = xv[1].x * qv[1].x + xv[1].y * qv[1].y + xv[1].z * qv[1].z + xv[1].w * qv[1].w;
        float e2 = xv[2].x * qv[2].x + xv[2].y * qv[2].y + xv[2].z * qv[2].z + xv[2].w * qv[2].w;
        float e3 = xv[3].x * qv[3].x + xv[3].y * qv[3].y + xv[3].z * qv[3].z + xv[3].w * qv[3].w;
        float e = (e0 + e1) + (e2 + e3);
        e += __shfl_xor_sync(0xffffffffu, e, 1);
        e += __shfl_xor_sync(0xffffffffu, e, 2);
        e += __shfl_xor_sync(0xffffffffu, e, 4);

        float ev = valid ? e : NEG_BIG;
        float mn = fmaxf(m, ev);
        float sc = ex2(m - mn);
        float p = ex2(ev - mn);
        p = valid ? p : 0.f;
        s = s * sc + p;
        #pragma unroll
        for (int j = 0; j < 4; j++) {
            acc[j].x = acc[j].x * sc + p * xv[j].x;
            acc[j].y = acc[j].y * sc + p * xv[j].y;
            acc[j].z = acc[j].z * sc + p * xv[j].z;
            acc[j].w = acc[j].w * sc + p * xv[j].w;
        }
        m = mn;
    }

    // fold the 4 row-groups within the warp (xor 8, xor 16)
    #pragma unroll
    for (int ofs = 8; ofs <= 16; ofs <<= 1) {
        float m2 = __shfl_xor_sync(0xffffffffu, m, ofs);
        float s2 = __shfl_xor_sync(0xffffffffu, s, ofs);
        float M2 = fmaxf(m, m2);
        float fa = ex2(m - M2), fb = ex2(m2 - M2);
        s = s * fa + s2 * fb;
        #pragma unroll
        for (int j = 0; j < 4; j++) {
            float ox = __shfl_xor_sync(0xffffffffu, acc[j].x, ofs);
            float oy = __shfl_xor_sync(0xffffffffu, acc[j].y, ofs);
            float oz = __shfl_xor_sync(0xffffffffu, acc[j].z, ofs);
            float ow = __shfl_xor_sync(0xffffffffu, acc[j].w, ofs);
            acc[j].x = acc[j].x * fa + ox * fb;
            acc[j].y = acc[j].y * fa + oy * fb;
            acc[j].z = acc[j].z * fa + oz * fb;
            acc[j].w = acc[j].w * fa + ow * fb;
        }
        m = M2;
    }

    __shared__ float sm_m[4], sm_s[4];
    __shared__ float sm_acc[4][128];
    if (l < 8) {
        #pragma unroll
        for (int j = 0; j < 4; j++) *(float4*)&sm_acc[w][i8 * 4 + 32 * j] = acc[j];
        if (l == 0) { sm_m[w] = m; sm_s[w] = s; }
    }
    __syncthreads();

    // t = column 0..127: combine 4 warps
    float M = fmaxf(fmaxf(sm_m[0], sm_m[1]), fmaxf(sm_m[2], sm_m[3]));
    float stot = 0.f, racc = 0.f;
    #pragma unroll
    for (int ww = 0; ww < 4; ww++) {
        float fsc = ex2(sm_m[ww] - M);
        stot += fsc * sm_s[ww];
        racc += fsc * sm_acc[ww][t];
    }
    float r = racc / fmaxf(stot, 1e-16f);
    if (FINAL) {
        out[(size_t)g * 256 + 128 + t] = r;
        out[(size_t)g * 256 + t] = qrow[t];
    } else {
        g_r[(size_t)g * D + t] = r;
    }
}

// ---------- launch ----------
extern "C" void kernel_launch(void* const* d_in, const int* in_sizes, int n_in,
                              void* d_out, int out_size) {
    const float* x    = (const float*)d_in[0];
    const float* W_ih = (const float*)d_in[1];
    const float* W_hh = (const float*)d_in[2];
    const float* b_ih = (const float*)d_in[3];
    const float* b_hh = (const float*)d_in[4];
    const int*   idx  = (const int*)d_in[5];
    float* out = (float*)d_out;
    int N = in_sizes[5];
    (void)n_in; (void)out_size;

    prep_weights<<<(256 * 512 + 255) / 256, 256>>>(W_ih, W_hh, b_ih, b_hh);
    seg_bounds<<<(G + 1 + 255) / 256, 256>>>(idx, N);
    step1_vec<<<1, 128>>>();

    // step 1: q = h1 (broadcast) -> r1
    attn_kernel<true, false><<<G, 128>>>(x, out);

    // step 2: gates = g1base + r1 @ WcT[128:256], fused LSTM -> h2, c2
    g1base_kernel<<<1, 512>>>();
    gemm_lstm<false, true><<<dim3(32, 4), 256>>>();
    attn_kernel<false, false><<<G, 128>>>(x, out);

    // step 3: gates = bias + h2 @ WcT[0:128] + r2 @ WcT[128:256], fused LSTM -> h3, c3
    gemm_lstm<true, false><<<dim3(32, 4), 256>>>();
    attn_kernel<false, true><<<G, 128>>>(x, out);
}